// round 6
// baseline (speedup 1.0000x reference)
#include <cuda_runtime.h>

// ---------------- problem constants ----------------
#define C_CH   256
#define H_BEV  200
#define W_BEV  704
#define HW     (H_BEV * W_BEV)     // 140800
#define HW4    (HW / 4)            // 35200
#define A_NUM  2
#define NC_NUM 4
#define K_SEL  20000
#define NSLOT  (A_NUM * HW)        // 281600  (flat A*H*W cells)
#define RM_OFF NSLOT               // rm starts after psm in d_out
#define NOUT16 16                  // 2 cls + 14 reg channels

// packed winner table: high32 = float bits of peer score (positive -> monotonic),
// low32 = ((3 - cav_idx) << 16) | k.  0 == no peer selected this cell.
__device__ unsigned long long g_slots[NSLOT];

// ---------------- f32x2 helpers ----------------
__device__ __forceinline__ unsigned long long pack2(float lo, float hi) {
    unsigned long long r;
    asm("mov.b64 %0, {%1, %2};" : "=l"(r) : "f"(lo), "f"(hi));
    return r;
}
__device__ __forceinline__ void unpack2(unsigned long long v, float& lo, float& hi) {
    asm("mov.b64 {%0, %1}, %2;" : "=f"(lo), "=f"(hi) : "l"(v));
}
__device__ __forceinline__ unsigned long long fma2(unsigned long long a,
                                                   unsigned long long b,
                                                   unsigned long long c) {
    asm("fma.rn.f32x2 %0, %1, %2, %3;" : "=l"(c) : "l"(a), "l"(b), "l"(c));
    return c;
}

// ---------------- kernel 1: zero the winner table ----------------
__global__ void k_init_slots() {
    int t = blockIdx.x * blockDim.x + threadIdx.x;
    if (t < NSLOT) g_slots[t] = 0ULL;
}

// ---------------- kernel 2: scatter peer candidates ----------------
__global__ void k_scatter(const int* __restrict__ mask_idx,
                          const float* __restrict__ scores) {
    int t = blockIdx.x * blockDim.x + threadIdx.x;
    if (t >= NC_NUM * K_SEL) return;
    int i = t / K_SEL;
    int k = t - i * K_SEL;                       // k < 20000 < 2^16
    int f = mask_idx[t];                         // flat index in [0, A*H*W)
    unsigned long long key =
        ((unsigned long long)__float_as_uint(scores[t]) << 32) |
        ((unsigned long long)(3 - i) << 16) | (unsigned)k;
    atomicMax(&g_slots[f], key);
}

// ---------------- kernel 3: fused heads + select + gather ----------------
// grid: 275 blocks x 128 threads == 35200 threads == HW/4 pixel-quads (exact)
__global__ __launch_bounds__(128)
void k_main(const float4* __restrict__ feat4,    // [C, HW/4] as float4
            const float*  __restrict__ cls_w,    // [2, 256]
            const float*  __restrict__ cls_b,    // [2]
            const float*  __restrict__ reg_w,    // [14, 256]
            const float*  __restrict__ reg_b,    // [14]
            const float*  __restrict__ psm_v2x,  // [4, 20000]
            const float*  __restrict__ rm_v2x,   // [4, 7*20000]
            float*        __restrict__ out) {    // [psm 281600 | rm 1971200]
    // weights duplicated into (w,w) f32x2 pairs, channel-major for broadcast LDS
    __shared__ unsigned long long w2[C_CH][NOUT16];          // 32 KB
    for (int idx = threadIdx.x; idx < C_CH * NOUT16; idx += blockDim.x) {
        int c = idx >> 4, o = idx & 15;
        float wv = (o < A_NUM) ? cls_w[o * C_CH + c]
                               : reg_w[(o - A_NUM) * C_CH + c];
        w2[c][o] = pack2(wv, wv);
    }
    __syncthreads();

    int p4 = blockIdx.x * blockDim.x + threadIdx.x;          // pixel-quad id

    unsigned long long acc[NOUT16][2];
#pragma unroll
    for (int o = 0; o < NOUT16; ++o) { acc[o][0] = 0ULL; acc[o][1] = 0ULL; }

#pragma unroll 8
    for (int c = 0; c < C_CH; ++c) {
        float4 x = feat4[c * HW4 + p4];                      // coalesced 16B
        unsigned long long x01 = pack2(x.x, x.y);
        unsigned long long x23 = pack2(x.z, x.w);
#pragma unroll
        for (int o = 0; o < NOUT16; ++o) {
            unsigned long long w = w2[c][o];                 // broadcast LDS.64
            acc[o][0] = fma2(x01, w, acc[o][0]);
            acc[o][1] = fma2(x23, w, acc[o][1]);
        }
    }

    float v[NOUT16][4];
#pragma unroll
    for (int o = 0; o < NOUT16; ++o) {
        unpack2(acc[o][0], v[o][0], v[o][1]);
        unpack2(acc[o][1], v[o][2], v[o][3]);
    }

    int p = p4 * 4;
#pragma unroll
    for (int a = 0; a < A_NUM; ++a) {
        float cb = cls_b[a];
#pragma unroll
        for (int j = 0; j < 4; ++j) {
            int hw = p + j;
            int f  = a * HW + hw;
            float psm_ego = v[a][j] + cb;
            float prob    = 1.0f / (1.0f + expf(-psm_ego));  // sigmoid, fp32

            unsigned long long key = g_slots[f];
            bool peer = false;
            int ci = 0, ck = 0;
            if (key != 0ULL) {
                float s = __uint_as_float((unsigned)(key >> 32));
                if (s > prob) {                   // strict >: ego wins ties (argmax first-max)
                    peer = true;
                    unsigned lo = (unsigned)key;
                    ck = (int)(lo & 0xFFFFu);
                    ci = 3 - (int)((lo >> 16) & 0xFFFFu);
                }
            }

            out[f] = peer ? psm_v2x[ci * K_SEL + ck] : psm_ego;

#pragma unroll
            for (int r = 0; r < 7; ++r) {
                int rc = 2 * r + a;               // rm channel using anchor-a winner
                float ego = v[A_NUM + rc][j] + reg_b[rc];
                out[RM_OFF + rc * HW + hw] =
                    peer ? rm_v2x[(ci * 7 + r) * K_SEL + ck] : ego;
            }
        }
    }
}

// ---------------- launch ----------------
extern "C" void kernel_launch(void* const* d_in, const int* in_sizes, int n_in,
                              void* d_out, int out_size) {
    const float4* feat4    = (const float4*)d_in[0];  // [1,256,200,704] f32
    const float*  cls_w    = (const float*)d_in[1];   // [2,256]
    const float*  cls_b    = (const float*)d_in[2];   // [2]
    const float*  reg_w    = (const float*)d_in[3];   // [14,256]
    const float*  reg_b    = (const float*)d_in[4];   // [14]
    const float*  psm_v2x  = (const float*)d_in[5];   // [4,20000]
    const float*  rm_v2x   = (const float*)d_in[6];   // [4,140000]
    const float*  scores   = (const float*)d_in[7];   // [4,20000]
    const int*    mask_idx = (const int*)d_in[8];     // [4,20000]
    // d_in[9] = mask_reg_idx: derivable (f + r*A*H*W), unused.
    float* out = (float*)d_out;

    k_init_slots<<<(NSLOT + 255) / 256, 256>>>();
    k_scatter<<<(NC_NUM * K_SEL + 255) / 256, 256>>>(mask_idx, scores);
    k_main<<<HW4 / 128, 128>>>(feat4, cls_w, cls_b, reg_w, reg_b,
                               psm_v2x, rm_v2x, out);
}

// round 7
// speedup vs baseline: 1.5339x; 1.5339x over previous
#include <cuda_runtime.h>

// ---------------- problem constants ----------------
#define C_CH   256
#define H_BEV  200
#define W_BEV  704
#define HW     (H_BEV * W_BEV)     // 140800
#define HW2    (HW / 2)            // 70400
#define A_NUM  2
#define NC_NUM 4
#define K_SEL  20000
#define NSLOT  (A_NUM * HW)        // 281600 flat A*H*W cells
#define RM_OFF NSLOT               // rm starts after psm in d_out
#define NOUT16 16                  // 2 cls + 14 reg channels

// packed winner table: high32 = float bits of peer score (positive -> monotonic),
// low32 = ((3 - cav_idx) << 16) | k.  0 == no peer selected this cell.
__device__ __align__(16) unsigned long long g_slots[NSLOT];

// ---------------- f32x2 helpers ----------------
__device__ __forceinline__ unsigned long long pack2(float lo, float hi) {
    unsigned long long r;
    asm("mov.b64 %0, {%1, %2};" : "=l"(r) : "f"(lo), "f"(hi));
    return r;
}
__device__ __forceinline__ void unpack2(unsigned long long v, float& lo, float& hi) {
    asm("mov.b64 {%0, %1}, %2;" : "=f"(lo), "=f"(hi) : "l"(v));
}
__device__ __forceinline__ unsigned long long fma2(unsigned long long a,
                                                   unsigned long long b,
                                                   unsigned long long c) {
    asm("fma.rn.f32x2 %0, %1, %2, %3;" : "=l"(c) : "l"(a), "l"(b), "l"(c));
    return c;
}

// ---------------- kernel 1: scatter peer candidates ----------------
__global__ void k_scatter(const int* __restrict__ mask_idx,
                          const float* __restrict__ scores) {
    int t = blockIdx.x * blockDim.x + threadIdx.x;
    if (t >= NC_NUM * K_SEL) return;
    int i = t / K_SEL;
    int k = t - i * K_SEL;                       // k < 20000 < 2^16
    int f = mask_idx[t];                         // flat index in [0, A*H*W)
    unsigned long long key =
        ((unsigned long long)__float_as_uint(scores[t]) << 32) |
        ((unsigned long long)(3 - i) << 16) | (unsigned)k;
    atomicMax(&g_slots[f], key);
}

// ---------------- kernel 2: fused heads + select + gather ----------------
// 2 pixels per thread: 70400 threads = 550 blocks x 128
__global__ __launch_bounds__(128)
void k_main(const float2* __restrict__ feat2,    // [C, HW/2] as float2
            const float*  __restrict__ cls_w,    // [2, 256]
            const float*  __restrict__ cls_b,    // [2]
            const float*  __restrict__ reg_w,    // [14, 256]
            const float*  __restrict__ reg_b,    // [14]
            const float*  __restrict__ psm_v2x,  // [4, 20000]
            const float*  __restrict__ rm_v2x,   // [4, 7*20000]
            float*        __restrict__ out) {    // [psm 281600 | rm 1971200]
    // weights duplicated into (w,w) f32x2 pairs; pairs of outputs packed into
    // ulonglong2 so one broadcast LDS.128 feeds two FFMA2s.
    __shared__ __align__(16) ulonglong2 w2v[C_CH][NOUT16 / 2];   // 32 KB
    for (int idx = threadIdx.x; idx < C_CH * NOUT16; idx += blockDim.x) {
        int c = idx >> 4, o = idx & 15;
        float wv = (o < A_NUM) ? cls_w[o * C_CH + c]
                               : reg_w[(o - A_NUM) * C_CH + c];
        ((unsigned long long*)&w2v[c][0])[o] = pack2(wv, wv);
    }
    __syncthreads();

    int p2 = blockIdx.x * blockDim.x + threadIdx.x;          // pixel-pair id

    unsigned long long acc[NOUT16];
#pragma unroll
    for (int o = 0; o < NOUT16; ++o) acc[o] = 0ULL;

#pragma unroll 8
    for (int c = 0; c < C_CH; ++c) {
        float2 x = feat2[c * HW2 + p2];                      // coalesced 8B
        unsigned long long x01 = pack2(x.x, x.y);
#pragma unroll
        for (int o2 = 0; o2 < NOUT16 / 2; ++o2) {
            ulonglong2 w = w2v[c][o2];                       // broadcast LDS.128
            acc[2 * o2]     = fma2(x01, w.x, acc[2 * o2]);
            acc[2 * o2 + 1] = fma2(x01, w.y, acc[2 * o2 + 1]);
        }
    }

    float v[NOUT16][2];
#pragma unroll
    for (int o = 0; o < NOUT16; ++o) unpack2(acc[o], v[o][0], v[o][1]);

    int p = p2 * 2;
#pragma unroll
    for (int a = 0; a < A_NUM; ++a) {
        float cb = cls_b[a];
        // slot pair for this anchor's two pixels (16B aligned: p even)
        ulonglong2 keys = *(const ulonglong2*)&g_slots[a * HW + p];

        bool  peer[2];
        int   ci[2], ck[2];
        float psm_o[2];
#pragma unroll
        for (int j = 0; j < 2; ++j) {
            float psm_ego = v[a][j] + cb;
            float prob    = 1.0f / (1.0f + expf(-psm_ego));  // sigmoid, fp32
            unsigned long long key = (j == 0) ? keys.x : keys.y;
            peer[j] = false; ci[j] = 0; ck[j] = 0;
            if (key != 0ULL) {
                float s = __uint_as_float((unsigned)(key >> 32));
                if (s > prob) {              // strict >: ego wins ties (argmax first-max)
                    peer[j] = true;
                    unsigned lo = (unsigned)key;
                    ck[j] = (int)(lo & 0xFFFFu);
                    ci[j] = 3 - (int)((lo >> 16) & 0xFFFFu);
                }
            }
            psm_o[j] = peer[j] ? psm_v2x[ci[j] * K_SEL + ck[j]] : psm_ego;
        }
        *(float2*)&out[a * HW + p] = make_float2(psm_o[0], psm_o[1]);

#pragma unroll
        for (int r = 0; r < 7; ++r) {
            int rc = 2 * r + a;              // rm channel using anchor-a winner
            float rb = reg_b[rc];
            float r0 = peer[0] ? rm_v2x[(ci[0] * 7 + r) * K_SEL + ck[0]]
                               : v[A_NUM + rc][0] + rb;
            float r1 = peer[1] ? rm_v2x[(ci[1] * 7 + r) * K_SEL + ck[1]]
                               : v[A_NUM + rc][1] + rb;
            *(float2*)&out[RM_OFF + rc * HW + p] = make_float2(r0, r1);
        }
    }
}

// ---------------- launch ----------------
extern "C" void kernel_launch(void* const* d_in, const int* in_sizes, int n_in,
                              void* d_out, int out_size) {
    const float2* feat2    = (const float2*)d_in[0];  // [1,256,200,704] f32
    const float*  cls_w    = (const float*)d_in[1];   // [2,256]
    const float*  cls_b    = (const float*)d_in[2];   // [2]
    const float*  reg_w    = (const float*)d_in[3];   // [14,256]
    const float*  reg_b    = (const float*)d_in[4];   // [14]
    const float*  psm_v2x  = (const float*)d_in[5];   // [4,20000]
    const float*  rm_v2x   = (const float*)d_in[6];   // [4,140000]
    const float*  scores   = (const float*)d_in[7];   // [4,20000]
    const int*    mask_idx = (const int*)d_in[8];     // [4,20000]
    // d_in[9] = mask_reg_idx: derivable (f + r*A*H*W), unused.
    float* out = (float*)d_out;

    // zero the winner table via a graph memset node (no kernel launch cost)
    void* slots_ptr = nullptr;
    cudaGetSymbolAddress(&slots_ptr, g_slots);
    cudaMemsetAsync(slots_ptr, 0, NSLOT * sizeof(unsigned long long));

    k_scatter<<<(NC_NUM * K_SEL + 255) / 256, 256>>>(mask_idx, scores);
    k_main<<<HW2 / 128, 128>>>(feat2, cls_w, cls_b, reg_w, reg_b,
                               psm_v2x, rm_v2x, out);
}